// round 8
// baseline (speedup 1.0000x reference)
#include <cuda_runtime.h>
#include <cuda_bf16.h>
#include <cstdint>

#define NPIX 262144               // 512*512 = 2^18
#define HALFCNT 4194304u          // 2^22 threefry counter half
#define GBLK 512                  // k_gramA blocks (512 px each)

// ---------------- device scratch (allocation-free) ----------------
__device__ float g_xt[4 * 210];
__device__ float g_acoef[4 * 8 * 2 * 6];  // [b][r][j][bb0,bb1,p,q,u,v]
__device__ float g_wr[4 * 8];
__device__ float g_part[4 * 44 * GBLK];   // gram partials [b*44+j][blk]
__device__ float g_Cc[4 * 8];
__device__ float g_Ff[4 * 8];
__device__ float g_Kk[4];
__device__ int   g_ctr;                   // last-block counter (reset each run)

// ---------------- packed f32x2 helpers (Blackwell) ----------------
__device__ __forceinline__ uint64_t pk2(float lo, float hi) {
  uint64_t r; asm("mov.b64 %0, {%1, %2};" : "=l"(r) : "f"(lo), "f"(hi)); return r;
}
__device__ __forceinline__ void upk2(uint64_t v, float& lo, float& hi) {
  asm("mov.b64 {%0, %1}, %2;" : "=f"(lo), "=f"(hi) : "l"(v));
}
__device__ __forceinline__ uint64_t bc2(float x) { return pk2(x, x); }
__device__ __forceinline__ uint64_t fma2(uint64_t a, uint64_t b, uint64_t c) {
  uint64_t d; asm("fma.rn.f32x2 %0, %1, %2, %3;" : "=l"(d) : "l"(a), "l"(b), "l"(c)); return d;
}
__device__ __forceinline__ uint64_t mul2(uint64_t a, uint64_t b) {
  uint64_t d; asm("mul.rn.f32x2 %0, %1, %2;" : "=l"(d) : "l"(a), "l"(b)); return d;
}
__device__ __forceinline__ uint64_t add2(uint64_t a, uint64_t b) {
  uint64_t d; asm("add.rn.f32x2 %0, %1, %2;" : "=l"(d) : "l"(a), "l"(b)); return d;
}

// ---------------- K0: fused xt + mods (last block does mods) ----------------
__global__ void k_pre(const float* __restrict__ x, const float* __restrict__ cw,
                      const float* __restrict__ cb) {
  int f = blockIdx.x;          // 0..209
  int t = threadIdx.x;         // 128
  {
    const float* wrow = cw + f * 512;
    float a0 = 0.f, a1 = 0.f, a2 = 0.f, a3 = 0.f;
    for (int i = t; i < 512; i += 128) {
      float w = wrow[i];
      a0 = fmaf(w, x[i], a0);
      a1 = fmaf(w, x[512 + i], a1);
      a2 = fmaf(w, x[1024 + i], a2);
      a3 = fmaf(w, x[1536 + i], a3);
    }
#pragma unroll
    for (int o = 16; o; o >>= 1) {
      a0 += __shfl_xor_sync(~0u, a0, o);
      a1 += __shfl_xor_sync(~0u, a1, o);
      a2 += __shfl_xor_sync(~0u, a2, o);
      a3 += __shfl_xor_sync(~0u, a3, o);
    }
    __shared__ float sm[4][4];
    int wq = t >> 5, l = t & 31;
    if (l == 0) { sm[wq][0] = a0; sm[wq][1] = a1; sm[wq][2] = a2; sm[wq][3] = a3; }
    __syncthreads();
    if (t == 0) {
      float bb = cb[f];
#pragma unroll
      for (int b = 0; b < 4; b++)
        g_xt[b * 210 + f] = sm[0][b] + sm[1][b] + sm[2][b] + sm[3][b] + bb;
    }
  }
  __threadfence();
  __shared__ int slast;
  if (t == 0) slast = (atomicAdd(&g_ctr, 1) == 209);
  __syncthreads();
  if (!slast) return;
  // ---- last block: mods ----
  __threadfence();
  if (t == 0) g_ctr = 0;  // reset for graph replay
  __shared__ float gated[4][105];
  for (int i = t; i < 420; i += 128) {
    int b = i / 105, k = i - 105 * b;
    float a1 = g_xt[b * 210 + k], a2 = g_xt[b * 210 + 105 + k];
    gated[b][k] = a1 * tanhf(a2);
  }
  __syncthreads();
  if (t < 64) {
    int b = t >> 4, r = (t >> 1) & 7, j = t & 1;
    int base = r * 12 + j * 2;
    float c0 = gated[b][base + 0] + 0.5f;
    float c1 = gated[b][base + 1];
    float bb0 = gated[b][base + 4];
    float bb1 = gated[b][base + 5];
    float s0 = gated[b][base + 8] + 1.0f;
    float s1 = gated[b][base + 9];
    float omc = 1.0f - c0;
    float p = s0 * omc + s1 * c1;
    float q = s0 * c1 - s1 * omc;
    float u = s0 * c0 - s1 * c1;
    float v = -(s0 * c1 + s1 * c0);
    float* dst = &g_acoef[((b * 8 + r) * 2 + j) * 6];
    dst[0] = bb0; dst[1] = bb1; dst[2] = p; dst[3] = q; dst[4] = u; dst[5] = v;
  }
  if (t < 4) {
    int b = t;
    float w[9];
#pragma unroll
    for (int i = 0; i < 9; i++) w[i] = gated[b][96 + i];
    w[8] += 0.35355339059327373f;  // 1/sqrt(8)
    float ss = 0.f;
#pragma unroll
    for (int i = 0; i < 9; i++) ss += w[i] * w[i];
    float inv = 1.0f / fmaxf(sqrtf(ss), 1e-12f);
    float mx = -3.4e38f;
#pragma unroll
    for (int i = 0; i < 9; i++) { w[i] *= inv; mx = fmaxf(mx, w[i]); }
    float sum = 0.f;
#pragma unroll
    for (int i = 0; i < 9; i++) { w[i] = expf(w[i] - mx); sum += w[i]; }
    float isum = 1.0f / sum;
#pragma unroll
    for (int i = 0; i < 8; i++) g_wr[b * 8 + i] = w[i] * isum;
  }
}

// ---------------- packed coef table builder (16 per (b,r)) ----------------
// layout [br*16 + j*8 + k]: k=0..5 -> {bb0,bb1,p,q,u,v}; k=6 -> -q; k=7 -> -v
__device__ __forceinline__ void build_scf2(uint64_t* scf2, int t, int nthr) {
  for (int i = t; i < 512; i += nthr) {
    int br = i >> 4, k = i & 15;
    int j = (k >> 3) & 1, kk = k & 7;
    const float* c = &g_acoef[(br * 2 + j) * 6];
    float v = (kk < 6) ? c[kk] : ((kk == 6) ? -c[3] : -c[5]);
    scf2[i] = pk2(v, v);
  }
}

// packed wval over a pixel pair; s points at the 16-entry packed coef row
__device__ __forceinline__ uint64_t wval2(const uint64_t* __restrict__ s,
    uint64_t are, uint64_t aim, uint64_t bre, uint64_t bim,
    uint64_t cre, uint64_t cim, uint64_t dre, uint64_t dim_) {
  uint64_t nr = fma2(s[2], are, s[0]);
  nr = fma2(s[3], aim, nr); nr = fma2(s[4], bre, nr); nr = fma2(s[5], bim, nr);
  uint64_t ni = fma2(s[6], are, s[1]);
  ni = fma2(s[2], aim, ni); ni = fma2(s[7], bre, ni); ni = fma2(s[4], bim, ni);
  uint64_t er = fma2(s[10], cre, s[8]);
  er = fma2(s[11], cim, er); er = fma2(s[12], dre, er); er = fma2(s[13], dim_, er);
  uint64_t ei = fma2(s[14], cre, s[9]);
  ei = fma2(s[10], cim, ei); ei = fma2(s[15], dre, ei); ei = fma2(s[12], dim_, ei);
  uint64_t d2 = fma2(ei, ei, mul2(er, er));
  float dl, dh; upk2(d2, dl, dh);
  uint64_t inv = pk2(rsqrtf(fmaxf(dl, 1e-12f)), rsqrtf(fmaxf(dh, 1e-12f)));
  uint64_t dot = fma2(ni, ei, mul2(nr, er));
  return mul2(dot, inv);
}

// triangular pair index: s <= t
#define TIDX(s, t) ((s) * 8 - (s) * ((s)-1) / 2 + ((t) - (s)))

// ---------------- K1: fused w-compute + Gram ----------------
__global__ void __launch_bounds__(256) k_gramA(const float* __restrict__ wt) {
  extern __shared__ float dyn[];
  float* sw = dyn;                               // 32*512 floats (64KB)
  uint64_t* scf2 = (uint64_t*)(dyn + 32 * 512);  // 512 packed coefs (4KB)
  __shared__ float red[8][44];
  int t = threadIdx.x;
  build_scf2(scf2, t, 256);
  __syncthreads();
  // ---- phase 1: packed w for pixel pair ----
  int q = blockIdx.x * 256 + t;             // float4 index within plane
  const float4* W4 = (const float4*)wt;
#pragma unroll
  for (int r = 0; r < 8; r++) {
    float4 A0 = W4[(size_t)(4 * r + 0) * (NPIX / 2) + q];
    float4 A1 = W4[(size_t)(4 * r + 1) * (NPIX / 2) + q];
    float4 B0 = W4[(size_t)(4 * r + 2) * (NPIX / 2) + q];
    float4 B1 = W4[(size_t)(4 * r + 3) * (NPIX / 2) + q];
    uint64_t are = pk2(A0.x, A0.z), aim = pk2(A0.y, A0.w);
    uint64_t bre = pk2(B0.x, B0.z), bim = pk2(B0.y, B0.w);
    uint64_t cre = pk2(A1.x, A1.z), cim = pk2(A1.y, A1.w);
    uint64_t dre = pk2(B1.x, B1.z), dim_ = pk2(B1.y, B1.w);
#pragma unroll
    for (int b = 0; b < 4; b++) {
      uint64_t w2 = wval2(&scf2[(b * 8 + r) * 16], are, aim, bre, bim, cre, cim, dre, dim_);
      ((uint64_t*)sw)[(b * 8 + r) * 256 + t] = w2;  // == float2{w0,w1}
    }
  }
  __syncthreads();
  // ---- phase 2: per-batch Gram + sums from smem (scalar) ----
  int wq = t >> 5, lane = t & 31;
  int b = wq >> 1, half = wq & 1;
  float a[36], su[8];
#pragma unroll
  for (int k = 0; k < 36; k++) a[k] = 0.f;
#pragma unroll
  for (int k = 0; k < 8; k++) su[k] = 0.f;
#pragma unroll
  for (int k = 0; k < 8; k++) {
    int px = half * 256 + k * 32 + lane;
    float v[8];
#pragma unroll
    for (int s = 0; s < 8; s++) v[s] = sw[(b * 8 + s) * 512 + px];
#pragma unroll
    for (int s = 0; s < 8; s++) {
      su[s] += v[s];
#pragma unroll
      for (int u = s; u < 8; u++) a[TIDX(s, u)] = fmaf(v[s], v[u], a[TIDX(s, u)]);
    }
  }
#pragma unroll
  for (int k = 0; k < 36; k++)
#pragma unroll
    for (int o = 16; o; o >>= 1) a[k] += __shfl_xor_sync(~0u, a[k], o);
#pragma unroll
  for (int k = 0; k < 8; k++)
#pragma unroll
    for (int o = 16; o; o >>= 1) su[k] += __shfl_xor_sync(~0u, su[k], o);
  if (lane == 0) {
#pragma unroll
    for (int k = 0; k < 36; k++) red[wq][k] = a[k];
#pragma unroll
    for (int k = 0; k < 8; k++) red[wq][36 + k] = su[k];
  }
  __syncthreads();
  if (t < 176) {
    int bb = t / 44, j = t - 44 * bb;
    g_part[(size_t)(bb * 44 + j) * GBLK + blockIdx.x] =
        red[2 * bb][j] + red[2 * bb + 1][j];
  }
}

// ---------------- K2: reduce partials + finalize (4 blocks) ----------------
__global__ void __launch_bounds__(256) k_redfin() {
  int b = blockIdx.x;              // 0..3
  int t = threadIdx.x;             // 256 = 8 warps
  int wq = t >> 5, lane = t & 31;
  __shared__ float sG[44];
  for (int j = wq; j < 44; j += 8) {
    const float* p = &g_part[(size_t)(b * 44 + j) * GBLK];
    float acc = 0.f;
#pragma unroll
    for (int k = 0; k < GBLK / 32; k++) acc += p[k * 32 + lane];
#pragma unroll
    for (int o = 16; o; o >>= 1) acc += __shfl_xor_sync(~0u, acc, o);
    if (lane == 0) sG[j] = acc;
  }
  __syncthreads();
  if (t == 0) {
    float G[8][8], S[8];
#pragma unroll
    for (int s = 0; s < 8; s++)
#pragma unroll
      for (int u = s; u < 8; u++) { float g = sG[TIDX(s, u)]; G[s][u] = g; G[u][s] = g; }
#pragma unroll
    for (int s = 0; s < 8; s++) S[s] = sG[36 + s];
    float nc[8];
#pragma unroll
    for (int s = 0; s < 8; s++) nc[s] = fmaxf(sqrtf(G[s][s]), 1e-12f);
    float Gh[8][8];
#pragma unroll
    for (int s = 0; s < 8; s++)
#pragma unroll
      for (int u = 0; u < 8; u++) Gh[s][u] = G[s][u] / (nc[s] * nc[u]);
    const float alpha = 0.1f / (7.0f * 2.8284271247461903f);  // 0.1/(7*sqrt(8))
    float A[8][8];
#pragma unroll
    for (int s = 0; s < 8; s++)
#pragma unroll
      for (int u = 0; u < 8; u++) A[s][u] = (s == u) ? 1.0f : -alpha * Gh[s][u];
    float C[8], K = 0.f;
#pragma unroll
    for (int s = 0; s < 8; s++) C[s] = 0.f;
#pragma unroll
    for (int r = 0; r < 8; r++) {
      float q = 0.f;
#pragma unroll
      for (int u = 0; u < 8; u++) {
        float v = 0.f;
#pragma unroll
        for (int s = 0; s < 8; s++) v += A[r][s] * Gh[s][u];
        q += v * A[r][u];
      }
      float mc = fmaxf(sqrtf(fmaxf(q, 0.f)), 1e-12f);
      double meand = 0.0;
      float wr = g_wr[b * 8 + r];
#pragma unroll
      for (int s = 0; s < 8; s++) {
        float D = A[r][s] / (nc[s] * mc);
        C[s] += wr * D;
        meand += (double)D * (double)S[s];
      }
      meand /= (double)NPIX;
      double var = (1.0 - (double)NPIX * meand * meand) / (double)(NPIX - 1);
      if (var < 0.0) var = 0.0;
      double stdd = sqrt(var);
      if (stdd < 1e-12) stdd = 1e-12;
      g_Ff[b * 8 + r] = 0.01f * wr * (float)stdd;
      K += 0.01f * wr * (float)meand;
    }
#pragma unroll
    for (int s = 0; s < 8; s++) g_Cc[b * 8 + s] = C[s];
    g_Kk[b] = K;
  }
}

// ---------------- threefry2x32 (JAX, key = [0, 42]) ----------------
__device__ __forceinline__ void threefry(uint32_t c0, uint32_t c1,
                                         uint32_t& o0, uint32_t& o1) {
  const uint32_t K0 = 0u, K1 = 42u, K2 = 0x1BD11BDAu ^ 0u ^ 42u;
  uint32_t x0 = c0 + K0, x1 = c1 + K1;
#define TFR(rr) { x0 += x1; x1 = __funnelshift_l(x1, x1, rr); x1 ^= x0; }
  TFR(13) TFR(15) TFR(26) TFR(6)   x0 += K1; x1 += K2 + 1u;
  TFR(17) TFR(29) TFR(16) TFR(24)  x0 += K2; x1 += K0 + 2u;
  TFR(13) TFR(15) TFR(26) TFR(6)   x0 += K0; x1 += K1 + 3u;
  TFR(17) TFR(29) TFR(16) TFR(24)  x0 += K1; x1 += K2 + 4u;
  TFR(13) TFR(15) TFR(26) TFR(6)   x0 += K2; x1 += K0 + 5u;
#undef TFR
  o0 = x0; o1 = x1;
}

// scalar path (exact XLA/Giles) — used only for the rare tail
__device__ __noinline__ float bits_to_normal(uint32_t bits) {
  float f = __uint_as_float((bits >> 9) | 0x3F800000u) - 1.0f;
  float x = fmaf(f, 2.0f, -0.99999994f);
  float w = -__logf(fmaf(x, -x, 1.0f));
  float p;
  if (w < 5.0f) {
    w -= 2.5f;
    p = 2.81022636e-08f;
    p = fmaf(p, w, 3.43273939e-07f);
    p = fmaf(p, w, -3.5233877e-06f);
    p = fmaf(p, w, -4.39150654e-06f);
    p = fmaf(p, w, 0.00021858087f);
    p = fmaf(p, w, -0.00125372503f);
    p = fmaf(p, w, -0.00417768164f);
    p = fmaf(p, w, 0.246640727f);
    p = fmaf(p, w, 1.50140941f);
  } else {
    w = sqrtf(w) - 3.0f;
    p = -0.000200214257f;
    p = fmaf(p, w, 0.000100950558f);
    p = fmaf(p, w, 0.00134934322f);
    p = fmaf(p, w, -0.00367342844f);
    p = fmaf(p, w, 0.00573950773f);
    p = fmaf(p, w, -0.0076224613f);
    p = fmaf(p, w, 0.00943887047f);
    p = fmaf(p, w, 1.00167406f);
    p = fmaf(p, w, 2.83297682f);
  }
  return 1.4142135623730951f * (p * x);
}

// packed normal for a pixel pair (ba -> lane lo, bb -> lane hi)
__device__ __forceinline__ uint64_t b2n2(uint32_t ba, uint32_t bb) {
  float fa = __uint_as_float((ba >> 9) | 0x3F800000u);
  float fb = __uint_as_float((bb >> 9) | 0x3F800000u);
  uint64_t f = add2(pk2(fa, fb), bc2(-1.0f));
  uint64_t x = fma2(f, bc2(2.0f), bc2(-0.99999994f));
  uint64_t xn = x ^ 0x8000000080000000ull;       // -x (both lanes)
  uint64_t tt = fma2(x, xn, bc2(1.0f));          // 1 - x^2 (fused, bit-exact)
  float tl, th; upk2(tt, tl, th);
  float wl = -__logf(tl), wh = -__logf(th);
  if (wl < 5.0f && wh < 5.0f) {
    uint64_t ww = add2(pk2(wl, wh), bc2(-2.5f));
    uint64_t p = bc2(2.81022636e-08f);
    p = fma2(p, ww, bc2(3.43273939e-07f));
    p = fma2(p, ww, bc2(-3.5233877e-06f));
    p = fma2(p, ww, bc2(-4.39150654e-06f));
    p = fma2(p, ww, bc2(0.00021858087f));
    p = fma2(p, ww, bc2(-0.00125372503f));
    p = fma2(p, ww, bc2(-0.00417768164f));
    p = fma2(p, ww, bc2(0.246640727f));
    p = fma2(p, ww, bc2(1.50140941f));
    return mul2(mul2(p, x), bc2(1.4142135623730951f));
  }
  return pk2(bits_to_normal(ba), bits_to_normal(bb));
}

// ---------------- K3: recompute-w combine + inline noise -> output ----------------
__global__ void __launch_bounds__(256) k_out(const float* __restrict__ wt,
                                             float* __restrict__ out) {
  __shared__ uint64_t scf2[512];
  __shared__ uint64_t sC2[32], sF2[32];
  __shared__ float sK[4];
  int t = threadIdx.x;
  build_scf2(scf2, t, 256);
  if (t < 32) { sC2[t] = pk2(g_Cc[t], g_Cc[t]); sF2[t] = pk2(g_Ff[t], g_Ff[t]); }
  if (t < 4) sK[t] = g_Kk[t];
  __syncthreads();
  int q = blockIdx.x * 256 + t;            // float4 index (pixels 2q, 2q+1)
  const float4* W4 = (const float4*)wt;
  uint64_t acc[4];
#pragma unroll
  for (int b = 0; b < 4; b++) acc[b] = bc2(sK[b]);
#pragma unroll
  for (int r = 0; r < 8; r++) {
    float4 A0 = W4[(size_t)(4 * r + 0) * (NPIX / 2) + q];
    float4 A1 = W4[(size_t)(4 * r + 1) * (NPIX / 2) + q];
    float4 B0 = W4[(size_t)(4 * r + 2) * (NPIX / 2) + q];
    float4 B1 = W4[(size_t)(4 * r + 3) * (NPIX / 2) + q];
    uint64_t are = pk2(A0.x, A0.z), aim = pk2(A0.y, A0.w);
    uint64_t bre = pk2(B0.x, B0.z), bim = pk2(B0.y, B0.w);
    uint64_t cre = pk2(A1.x, A1.z), cim = pk2(A1.y, A1.w);
    uint64_t dre = pk2(B1.x, B1.z), dim_ = pk2(B1.y, B1.w);
#pragma unroll
    for (int b = 0; b < 4; b++) {
      uint64_t w2 = wval2(&scf2[(b * 8 + r) * 16], are, aim, bre, bim, cre, cim, dre, dim_);
      acc[b] = fma2(sC2[b * 8 + r], w2, acc[b]);
    }
  }
  // inline noise: pixels n0 = 2q (lane lo), n0+1 (lane hi)
  uint32_t n0 = 2u * (uint32_t)q;
#pragma unroll
  for (int j = 0; j < 16; j++) {           // j = b2*8 + r, b2 in {0,1}
    uint32_t i0 = ((uint32_t)j << 18) | n0;
    uint32_t i1 = i0 + 1u;
    uint32_t a0, a1, b0, b1;
    threefry(i0, i0 + HALFCNT, a0, a1);
    threefry(i1, i1 + HALFCNT, b0, b1);
    uint64_t nA = b2n2(a0, b0);            // batch j>>3
    uint64_t nB = b2n2(a1, b1);            // batch (j>>3)+2
    int bb = j >> 3;
    acc[bb]     = fma2(sF2[j],      nA, acc[bb]);
    acc[bb + 2] = fma2(sF2[j + 16], nB, acc[bb + 2]);
  }
  uint64_t* O2 = (uint64_t*)out;           // float2 pairs
#pragma unroll
  for (int b = 0; b < 4; b++) O2[(size_t)b * (NPIX / 2) + q] = acc[b];
}

extern "C" void kernel_launch(void* const* d_in, const int* in_sizes, int n_in,
                              void* d_out, int out_size) {
  const float* x  = (const float*)d_in[0];
  const float* cw = (const float*)d_in[1];
  const float* cb = (const float*)d_in[2];
  const float* wt = (const float*)d_in[3];
  float* out = (float*)d_out;
  const int dynsmem = 32 * 512 * 4 + 512 * 8;  // 69632 B
  cudaFuncSetAttribute(k_gramA, cudaFuncAttributeMaxDynamicSharedMemorySize, dynsmem);
  k_pre<<<210, 128>>>(x, cw, cb);           // launch 1 (xt + mods fused)
  k_gramA<<<GBLK, 256, dynsmem>>>(wt);      // launch 2
  k_redfin<<<4, 256>>>();                   // launch 3
  k_out<<<NPIX / 512, 256>>>(wt, out);      // launch 4
}